// round 6
// baseline (speedup 1.0000x reference)
#include <cuda_runtime.h>

// LocSE fused kernel, round 6: R4 structure (best: scalar-broadcast smem
// activations + packed fma.rn.f32x2) with 768 threads/block -> 24 warps/SM
// (6 per SMSP) for latency hiding. Two-phase split staging the pre-relu MLP
// partial through d_out.

typedef unsigned long long ull;

__device__ __forceinline__ ull pk(float lo, float hi) {
    ull r; asm("mov.b64 %0, {%1, %2};" : "=l"(r) : "f"(lo), "f"(hi)); return r;
}
__device__ __forceinline__ void upk(ull v, float& lo, float& hi) {
    asm("mov.b64 {%0, %1}, %2;" : "=f"(lo), "=f"(hi) : "l"(v));
}
__device__ __forceinline__ ull fma2(ull a, ull b, ull c) {
#if __CUDA_ARCH__ >= 1000
    ull d; asm("fma.rn.f32x2 %0, %1, %2, %3;" : "=l"(d) : "l"(a), "l"(b), "l"(c));
    return d;
#else
    float ax, ay, bx, by, cx, cy;
    upk(a, ax, ay); upk(b, bx, by); upk(c, cx, cy);
    return pk(fmaf(ax, bx, cx), fmaf(ay, by, cy));
#endif
}
__device__ __forceinline__ ull dup2(float v) { return pk(v, v); }

// One residual conv layer: r = r + relu(conv1d(r + sum_c(r), W) + b)
// r: 9 packed accumulators (this lane's 2 output channels o = 2*lane, 2*lane+1)
// xb: per-warp smem buffer, 11 rows x 64 ch (rows 0 and 10 permanent zero pad)
__device__ __forceinline__ void conv_residual(ull r[9],
                                              const float* __restrict__ Wl,
                                              const float* __restrict__ bvec,
                                              float* __restrict__ xb, int lane)
{
    float s[9];
#pragma unroll
    for (int t = 0; t < 9; t++) { float lo, hi; upk(r[t], lo, hi); s[t] = lo + hi; }
#pragma unroll
    for (int off = 16; off >= 1; off >>= 1) {
#pragma unroll
        for (int t = 0; t < 9; t++) s[t] += __shfl_xor_sync(0xffffffffu, s[t], off);
    }
    __syncwarp();
#pragma unroll
    for (int t = 0; t < 9; t++) {
        float lo, hi; upk(r[t], lo, hi);
        *(ull*)(xb + (t + 1) * 64 + 2 * lane) = pk(lo + s[t], hi + s[t]);
    }
    __syncwarp();

    ull acc[9];
    ull b2 = *(const ull*)(bvec + 2 * lane);
#pragma unroll
    for (int t = 0; t < 9; t++) acc[t] = b2;

#pragma unroll 2
    for (int c = 0; c < 64; c++) {
        ull xd[11];
#pragma unroll
        for (int j = 0; j < 11; j++) xd[j] = dup2(xb[j * 64 + c]);
#pragma unroll
        for (int k = 0; k < 3; k++) {
            ull wk = *(const ull*)(Wl + (k * 64 + c) * 64 + 2 * lane);
#pragma unroll
            for (int t = 0; t < 9; t++) acc[t] = fma2(xd[t + k], wk, acc[t]);
        }
    }
#pragma unroll
    for (int t = 0; t < 9; t++) {
        float lo, hi; upk(acc[t], lo, hi);
        lo = fmaxf(lo, 0.f); hi = fmaxf(hi, 0.f);
        float rl, rh; upk(r[t], rl, rh);
        r[t] = pk(rl + lo, rh + hi);
    }
}

// am += xb(9x64) @ mws(64x64), weights in smem (conflict-free LDS.64)
__device__ __forceinline__ void mlp_pass(ull am[9], const float* __restrict__ xb,
                                         const float* __restrict__ mws, int lane)
{
#pragma unroll 4
    for (int c = 0; c < 64; c++) {
        ull w = *(const ull*)(mws + c * 64 + 2 * lane);
        ull xd[9];
#pragma unroll
        for (int t = 0; t < 9; t++) xd[t] = dup2(xb[(t + 1) * 64 + c]);
#pragma unroll
        for (int t = 0; t < 9; t++) am[t] = fma2(xd[t], w, am[t]);
    }
}

// ---------------------------------------------------------------------------
// Kernel 1: nrm tower + MLP half 1 -> out ch[0..63] (pre-relu) + feats copy
// ---------------------------------------------------------------------------
__global__ void __launch_bounds__(768, 1)
locse_k1(const float* __restrict__ pc, const float* __restrict__ feats,
         const float* __restrict__ nw0, const float* __restrict__ nb0,
         const float* __restrict__ nw1, const float* __restrict__ nb1,
         const float* __restrict__ nw2, const float* __restrict__ nb2,
         const float* __restrict__ mw, const float* __restrict__ mb,
         float* __restrict__ out, int ngroups)
{
    extern __shared__ float sm[];
    float* W   = sm;            // 2 * 12288 : [nrm_w1, nrm_w2]
    float* w0n = W + 24576;     // 192
    float* bia = w0n + 192;     // 192 : [nb0 nb1 nb2]
    float* mbs = bia + 192;     // 64
    float* mws = mbs + 64;      // 4096 : mlp_w rows 0..63
    float* xba = mws + 4096;    // 24 warps * 704 (11 rows x 64 ch)

    const int tid = threadIdx.x;
    for (int i = tid; i < 12288; i += 768) {
        W[i]         = nw1[i];
        W[12288 + i] = nw2[i];
    }
    for (int i = tid; i < 4096; i += 768) mws[i] = mw[i];
    if (tid < 192) w0n[tid] = nw0[tid];
    if (tid < 64) {
        bia[tid]       = nb0[tid];
        bia[64 + tid]  = nb1[tid];
        bia[128 + tid] = nb2[tid];
        mbs[tid]       = mb[tid];
    }
    const int warp = tid >> 5, lane = tid & 31;
    float* xb = xba + warp * 704;
    for (int i = lane; i < 64; i += 32) { xb[i] = 0.f; xb[640 + i] = 0.f; }
    __syncthreads();

    const int stride = gridDim.x * 24;
    for (int g = blockIdx.x * 24 + warp; g < ngroups; g += stride) {
        __syncwarp();
        if (lane < 9) {
            const float4 p  = *(const float4*)(pc + (size_t)g * 36 + lane * 4);
            const float4 cc = *(const float4*)(pc + (size_t)g * 36);
            float dx = cc.x - p.x;
            xb[(lane + 1) * 64] = 2.0f * dx;   // x + sum_c(x) with cin=1 -> 2x
        }
        __syncwarp();

        ull r[9];
        {
            ull b2 = *(const ull*)(bia + 2 * lane);
            ull acc[9];
#pragma unroll
            for (int t = 0; t < 9; t++) acc[t] = b2;
            float xv[11];
#pragma unroll
            for (int j = 0; j < 11; j++) xv[j] = xb[j * 64];
#pragma unroll
            for (int k = 0; k < 3; k++) {
                ull wk = *(const ull*)(w0n + k * 64 + 2 * lane);
#pragma unroll
                for (int t = 0; t < 9; t++) acc[t] = fma2(dup2(xv[t + k]), wk, acc[t]);
            }
#pragma unroll
            for (int t = 0; t < 9; t++) {
                float lo, hi; upk(acc[t], lo, hi);
                r[t] = pk(fmaxf(lo, 0.f), fmaxf(hi, 0.f));
            }
        }
        conv_residual(r, W,         bia + 64,  xb, lane);
        conv_residual(r, W + 12288, bia + 128, xb, lane);

        __syncwarp();
#pragma unroll
        for (int t = 0; t < 9; t++) *(ull*)(xb + (t + 1) * 64 + 2 * lane) = r[t];
        __syncwarp();

        ull am[9];
        {
            ull b2 = *(const ull*)(mbs + 2 * lane);
#pragma unroll
            for (int t = 0; t < 9; t++) am[t] = b2;
        }
        mlp_pass(am, xb, mws, lane);

        // stage pre-relu partial into out ch[0..63]; feats into ch[64..127]
        float* og = out + (size_t)g * 1152;
#pragma unroll
        for (int t = 0; t < 9; t++) *(ull*)(og + t * 128 + 2 * lane) = am[t];

        const float4* f4 = (const float4*)(feats + (size_t)g * 576);
        float4* o4 = (float4*)og;
        for (int i = lane; i < 144; i += 32) {
            int row = i >> 4, col = i & 15;
            o4[row * 32 + 16 + col] = f4[i];
        }
    }
}

// ---------------------------------------------------------------------------
// Kernel 2: ang tower + MLP half 2; out ch[0..63] += , then relu
// ---------------------------------------------------------------------------
__global__ void __launch_bounds__(768, 1)
locse_k2(const float* __restrict__ pc,
         const float* __restrict__ aw0, const float* __restrict__ ab0,
         const float* __restrict__ aw1, const float* __restrict__ ab1,
         const float* __restrict__ aw2, const float* __restrict__ ab2,
         const float* __restrict__ mw,
         float* __restrict__ out, int ngroups)
{
    extern __shared__ float sm[];
    float* W   = sm;            // 2 * 12288 : [ang_w1, ang_w2]
    float* w0a = W + 24576;     // 576
    float* bia = w0a + 576;     // 192 : [ab0 ab1 ab2]
    float* mws = bia + 192;     // 4096 : mlp_w rows 64..127
    float* xba = mws + 4096;    // 24 warps * 704

    const int tid = threadIdx.x;
    for (int i = tid; i < 12288; i += 768) {
        W[i]         = aw1[i];
        W[12288 + i] = aw2[i];
    }
    for (int i = tid; i < 4096; i += 768) mws[i] = mw[4096 + i];
    if (tid < 576) w0a[tid] = aw0[tid];
    if (tid < 64) {
        bia[tid]       = ab0[tid];
        bia[64 + tid]  = ab1[tid];
        bia[128 + tid] = ab2[tid];
    }
    const int warp = tid >> 5, lane = tid & 31;
    float* xb = xba + warp * 704;
    for (int i = lane; i < 64; i += 32) { xb[i] = 0.f; xb[640 + i] = 0.f; }
    __syncthreads();

    const int stride = gridDim.x * 24;
    for (int g = blockIdx.x * 24 + warp; g < ngroups; g += stride) {
        __syncwarp();
        if (lane < 9) {
            const float4 p  = *(const float4*)(pc + (size_t)g * 36 + lane * 4);
            const float4 cc = *(const float4*)(pc + (size_t)g * 36);
            float dx = cc.x - p.x, dy = cc.y - p.y;
            float s1 = p.x * p.x + p.y * p.y;
            float nrmv = (s1 > 0.f) ? sqrtf(s1) : 0.f;
            float s2 = dx * dx + dy * dy;
            float dn = (s2 > 0.f) ? sqrtf(s2) : 0.f;
            float s3 = cc.x * cc.x + cc.y * cc.y + cc.z * cc.z + cc.w * cc.w;
            float cn = (s3 > 0.f) ? sqrtf(s3) : 0.f;
            float num = dx * cc.z + dy * cc.w;
            float den = dn * cn + 1e-8f;
            float ang = 1.0f - fabsf(num / den);
            float ssum = dy + nrmv + ang;
            xb[(lane + 1) * 64 + 0] = dy + ssum;
            xb[(lane + 1) * 64 + 1] = nrmv + ssum;
            xb[(lane + 1) * 64 + 2] = ang + ssum;
        }
        __syncwarp();

        ull r[9];
        {
            ull b2 = *(const ull*)(bia + 2 * lane);
            ull acc[9];
#pragma unroll
            for (int t = 0; t < 9; t++) acc[t] = b2;
#pragma unroll
            for (int c = 0; c < 3; c++) {
                float xv[11];
#pragma unroll
                for (int j = 0; j < 11; j++) xv[j] = xb[j * 64 + c];
#pragma unroll
                for (int k = 0; k < 3; k++) {
                    ull wk = *(const ull*)(w0a + (k * 3 + c) * 64 + 2 * lane);
#pragma unroll
                    for (int t = 0; t < 9; t++) acc[t] = fma2(dup2(xv[t + k]), wk, acc[t]);
                }
            }
#pragma unroll
            for (int t = 0; t < 9; t++) {
                float lo, hi; upk(acc[t], lo, hi);
                r[t] = pk(fmaxf(lo, 0.f), fmaxf(hi, 0.f));
            }
        }
        conv_residual(r, W,         bia + 64,  xb, lane);
        conv_residual(r, W + 12288, bia + 128, xb, lane);

        __syncwarp();
#pragma unroll
        for (int t = 0; t < 9; t++) *(ull*)(xb + (t + 1) * 64 + 2 * lane) = r[t];
        __syncwarp();

        float* og = out + (size_t)g * 1152;
        ull am[9];
#pragma unroll
        for (int t = 0; t < 9; t++) am[t] = *(const ull*)(og + t * 128 + 2 * lane);
        mlp_pass(am, xb, mws, lane);

#pragma unroll
        for (int t = 0; t < 9; t++) {
            float lo, hi; upk(am[t], lo, hi);
            *(ull*)(og + t * 128 + 2 * lane) = pk(fmaxf(lo, 0.f), fmaxf(hi, 0.f));
        }
    }
}

extern "C" void kernel_launch(void* const* d_in, const int* in_sizes, int n_in,
                              void* d_out, int out_size)
{
    const float* pc    = (const float*)d_in[0];
    const float* feats = (const float*)d_in[1];
    // 2..13 = pos_* / rel_* (dead in the reference: pos_e/rel_e are discarded)
    const float* nw0 = (const float*)d_in[14];
    const float* nb0 = (const float*)d_in[15];
    const float* nw1 = (const float*)d_in[16];
    const float* nb1 = (const float*)d_in[17];
    const float* nw2 = (const float*)d_in[18];
    const float* nb2 = (const float*)d_in[19];
    const float* aw0 = (const float*)d_in[20];
    const float* ab0 = (const float*)d_in[21];
    const float* aw1 = (const float*)d_in[22];
    const float* ab1 = (const float*)d_in[23];
    const float* aw2 = (const float*)d_in[24];
    const float* ab2 = (const float*)d_in[25];
    const float* mw  = (const float*)d_in[26];
    const float* mb  = (const float*)d_in[27];

    const int ngroups = in_sizes[0] / 36;   // B*N groups of S=9 points x 4

    const int smem1 = (24576 + 192 + 192 + 64 + 4096 + 24 * 704) * 4;   // 184064
    const int smem2 = (24576 + 576 + 192 + 4096 + 24 * 704) * 4;        // 185344

    cudaFuncSetAttribute(locse_k1, cudaFuncAttributeMaxDynamicSharedMemorySize, smem1);
    cudaFuncSetAttribute(locse_k2, cudaFuncAttributeMaxDynamicSharedMemorySize, smem2);

    locse_k1<<<152, 768, smem1>>>(pc, feats, nw0, nb0, nw1, nb1, nw2, nb2,
                                  mw, mb, (float*)d_out, ngroups);
    locse_k2<<<152, 768, smem2>>>(pc, aw0, ab0, aw1, ab1, aw2, ab2,
                                  mw, (float*)d_out, ngroups);
}

// round 7
// speedup vs baseline: 1.6754x; 1.6754x over previous
#include <cuda_runtime.h>

// LocSE fused kernel, round 7: 768 threads (6 warps/SMSP) WITHOUT spills.
// Register diet vs R6: (a) r[] not held across the conv c-loop -- recomputed
// from xb (xb = r + s, s warp-uniform) after the loop; (b) zero-pad rows
// elided (9 activation loads, 25 FMA2 per c-iter instead of 11/27).
// Two-phase split (nrm+MLPhalf1 | ang+MLPhalf2) staging pre-relu via d_out.

typedef unsigned long long ull;

__device__ __forceinline__ ull pk(float lo, float hi) {
    ull r; asm("mov.b64 %0, {%1, %2};" : "=l"(r) : "f"(lo), "f"(hi)); return r;
}
__device__ __forceinline__ void upk(ull v, float& lo, float& hi) {
    asm("mov.b64 {%0, %1}, %2;" : "=f"(lo), "=f"(hi) : "l"(v));
}
__device__ __forceinline__ ull fma2(ull a, ull b, ull c) {
#if __CUDA_ARCH__ >= 1000
    ull d; asm("fma.rn.f32x2 %0, %1, %2, %3;" : "=l"(d) : "l"(a), "l"(b), "l"(c));
    return d;
#else
    float ax, ay, bx, by, cx, cy;
    upk(a, ax, ay); upk(b, bx, by); upk(c, cx, cy);
    return pk(fmaf(ax, bx, cx), fmaf(ay, by, cy));
#endif
}
__device__ __forceinline__ ull dup2(float v) { return pk(v, v); }

// One residual conv layer: r = r + relu(conv1d(r + sum_c(r), W) + b)
// On entry r[] holds this lane's 2 channels for 9 rows; on exit updated.
// xb: per-warp smem buffer, 11 rows x 64 ch (rows 0 and 10 permanent zero,
// never read here thanks to pad elision; kept for layer-0 compatibility).
__device__ __forceinline__ void conv_residual(ull r[9],
                                              const float* __restrict__ Wl,
                                              const float* __restrict__ bvec,
                                              float* __restrict__ xb, int lane)
{
    float s[9];
#pragma unroll
    for (int t = 0; t < 9; t++) { float lo, hi; upk(r[t], lo, hi); s[t] = lo + hi; }
#pragma unroll
    for (int off = 16; off >= 1; off >>= 1) {
#pragma unroll
        for (int t = 0; t < 9; t++) s[t] += __shfl_xor_sync(0xffffffffu, s[t], off);
    }
    __syncwarp();
#pragma unroll
    for (int t = 0; t < 9; t++) {
        float lo, hi; upk(r[t], lo, hi);
        *(ull*)(xb + (t + 1) * 64 + 2 * lane) = pk(lo + s[t], hi + s[t]);
    }
    __syncwarp();
    // r[] is dead from here until the tail -> ptxas can reuse its registers.

    ull acc[9];
    {
        ull b2 = *(const ull*)(bvec + 2 * lane);
#pragma unroll
        for (int t = 0; t < 9; t++) acc[t] = b2;
    }

#pragma unroll 2
    for (int c = 0; c < 64; c++) {
        ull xd[9];                               // padded rows 1..9 only
#pragma unroll
        for (int j = 0; j < 9; j++) xd[j] = dup2(xb[(j + 1) * 64 + c]);
#pragma unroll
        for (int k = 0; k < 3; k++) {
            ull wk = *(const ull*)(Wl + (k * 64 + c) * 64 + 2 * lane);
#pragma unroll
            for (int t = 0; t < 9; t++) {
                int row = t + k;                 // padded row index
                if (row >= 1 && row <= 9)        // compile-time pad elision
                    acc[t] = fma2(xd[row - 1], wk, acc[t]);
            }
        }
    }

    // tail: recover r = xb - s, add relu(acc)
#pragma unroll
    for (int t = 0; t < 9; t++) {
        ull xv = *(const ull*)(xb + (t + 1) * 64 + 2 * lane);
        float xlo, xhi; upk(xv, xlo, xhi);
        float alo, ahi; upk(acc[t], alo, ahi);
        r[t] = pk(xlo - s[t] + fmaxf(alo, 0.f),
                  xhi - s[t] + fmaxf(ahi, 0.f));
    }
}

// am += xb(rows 1..9 x 64) @ mws(64x64), weights in smem
__device__ __forceinline__ void mlp_pass(ull am[9], const float* __restrict__ xb,
                                         const float* __restrict__ mws, int lane)
{
#pragma unroll 4
    for (int c = 0; c < 64; c++) {
        ull w = *(const ull*)(mws + c * 64 + 2 * lane);
        ull xd[9];
#pragma unroll
        for (int t = 0; t < 9; t++) xd[t] = dup2(xb[(t + 1) * 64 + c]);
#pragma unroll
        for (int t = 0; t < 9; t++) am[t] = fma2(xd[t], w, am[t]);
    }
}

// ---------------------------------------------------------------------------
// Kernel 1: nrm tower + MLP half 1 -> out ch[0..63] (pre-relu) + feats copy
// ---------------------------------------------------------------------------
__global__ void __launch_bounds__(768, 1)
locse_k1(const float* __restrict__ pc, const float* __restrict__ feats,
         const float* __restrict__ nw0, const float* __restrict__ nb0,
         const float* __restrict__ nw1, const float* __restrict__ nb1,
         const float* __restrict__ nw2, const float* __restrict__ nb2,
         const float* __restrict__ mw, const float* __restrict__ mb,
         float* __restrict__ out, int ngroups)
{
    extern __shared__ float sm[];
    float* W   = sm;            // 2 * 12288 : [nrm_w1, nrm_w2]
    float* w0n = W + 24576;     // 192
    float* bia = w0n + 192;     // 192 : [nb0 nb1 nb2]
    float* mbs = bia + 192;     // 64
    float* mws = mbs + 64;      // 4096 : mlp_w rows 0..63
    float* xba = mws + 4096;    // 24 warps * 704 (11 rows x 64 ch)

    const int tid = threadIdx.x;
    for (int i = tid; i < 12288; i += 768) {
        W[i]         = nw1[i];
        W[12288 + i] = nw2[i];
    }
    for (int i = tid; i < 4096; i += 768) mws[i] = mw[i];
    if (tid < 192) w0n[tid] = nw0[tid];
    if (tid < 64) {
        bia[tid]       = nb0[tid];
        bia[64 + tid]  = nb1[tid];
        bia[128 + tid] = nb2[tid];
        mbs[tid]       = mb[tid];
    }
    const int warp = tid >> 5, lane = tid & 31;
    float* xb = xba + warp * 704;
    for (int i = lane; i < 64; i += 32) { xb[i] = 0.f; xb[640 + i] = 0.f; }
    __syncthreads();

    const int stride = gridDim.x * 24;
    for (int g = blockIdx.x * 24 + warp; g < ngroups; g += stride) {
        __syncwarp();
        if (lane < 9) {
            const float4 p  = *(const float4*)(pc + (size_t)g * 36 + lane * 4);
            const float4 cc = *(const float4*)(pc + (size_t)g * 36);
            float dx = cc.x - p.x;
            xb[(lane + 1) * 64] = 2.0f * dx;   // x + sum_c(x) with cin=1 -> 2x
        }
        __syncwarp();

        ull r[9];
        {
            ull b2 = *(const ull*)(bia + 2 * lane);
            ull acc[9];
#pragma unroll
            for (int t = 0; t < 9; t++) acc[t] = b2;
            float xv[9];                        // padded rows 1..9
#pragma unroll
            for (int j = 0; j < 9; j++) xv[j] = xb[(j + 1) * 64];
#pragma unroll
            for (int k = 0; k < 3; k++) {
                ull wk = *(const ull*)(w0n + k * 64 + 2 * lane);
#pragma unroll
                for (int t = 0; t < 9; t++) {
                    int row = t + k;
                    if (row >= 1 && row <= 9)
                        acc[t] = fma2(dup2(xv[row - 1]), wk, acc[t]);
                }
            }
#pragma unroll
            for (int t = 0; t < 9; t++) {
                float lo, hi; upk(acc[t], lo, hi);
                r[t] = pk(fmaxf(lo, 0.f), fmaxf(hi, 0.f));
            }
        }
        conv_residual(r, W,         bia + 64,  xb, lane);
        conv_residual(r, W + 12288, bia + 128, xb, lane);

        __syncwarp();
#pragma unroll
        for (int t = 0; t < 9; t++) *(ull*)(xb + (t + 1) * 64 + 2 * lane) = r[t];
        __syncwarp();

        ull am[9];
        {
            ull b2 = *(const ull*)(mbs + 2 * lane);
#pragma unroll
            for (int t = 0; t < 9; t++) am[t] = b2;
        }
        mlp_pass(am, xb, mws, lane);

        // stage pre-relu partial into out ch[0..63]; feats into ch[64..127]
        float* og = out + (size_t)g * 1152;
#pragma unroll
        for (int t = 0; t < 9; t++) *(ull*)(og + t * 128 + 2 * lane) = am[t];

        const float4* f4 = (const float4*)(feats + (size_t)g * 576);
        float4* o4 = (float4*)og;
        for (int i = lane; i < 144; i += 32) {
            int row = i >> 4, col = i & 15;
            o4[row * 32 + 16 + col] = f4[i];
        }
    }
}

// ---------------------------------------------------------------------------
// Kernel 2: ang tower + MLP half 2; out ch[0..63] += , then relu
// ---------------------------------------------------------------------------
__global__ void __launch_bounds__(768, 1)
locse_k2(const float* __restrict__ pc,
         const float* __restrict__ aw0, const float* __restrict__ ab0,
         const float* __restrict__ aw1, const float* __restrict__ ab1,
         const float* __restrict__ aw2, const float* __restrict__ ab2,
         const float* __restrict__ mw,
         float* __restrict__ out, int ngroups)
{
    extern __shared__ float sm[];
    float* W   = sm;            // 2 * 12288 : [ang_w1, ang_w2]
    float* w0a = W + 24576;     // 576
    float* bia = w0a + 576;     // 192 : [ab0 ab1 ab2]
    float* mws = bia + 192;     // 4096 : mlp_w rows 64..127
    float* xba = mws + 4096;    // 24 warps * 704

    const int tid = threadIdx.x;
    for (int i = tid; i < 12288; i += 768) {
        W[i]         = aw1[i];
        W[12288 + i] = aw2[i];
    }
    for (int i = tid; i < 4096; i += 768) mws[i] = mw[4096 + i];
    if (tid < 576) w0a[tid] = aw0[tid];
    if (tid < 64) {
        bia[tid]       = ab0[tid];
        bia[64 + tid]  = ab1[tid];
        bia[128 + tid] = ab2[tid];
    }
    const int warp = tid >> 5, lane = tid & 31;
    float* xb = xba + warp * 704;
    for (int i = lane; i < 64; i += 32) { xb[i] = 0.f; xb[640 + i] = 0.f; }
    __syncthreads();

    const int stride = gridDim.x * 24;
    for (int g = blockIdx.x * 24 + warp; g < ngroups; g += stride) {
        __syncwarp();
        if (lane < 9) {
            const float4 p  = *(const float4*)(pc + (size_t)g * 36 + lane * 4);
            const float4 cc = *(const float4*)(pc + (size_t)g * 36);
            float dx = cc.x - p.x, dy = cc.y - p.y;
            float s1 = p.x * p.x + p.y * p.y;
            float nrmv = (s1 > 0.f) ? sqrtf(s1) : 0.f;
            float s2 = dx * dx + dy * dy;
            float dn = (s2 > 0.f) ? sqrtf(s2) : 0.f;
            float s3 = cc.x * cc.x + cc.y * cc.y + cc.z * cc.z + cc.w * cc.w;
            float cn = (s3 > 0.f) ? sqrtf(s3) : 0.f;
            float num = dx * cc.z + dy * cc.w;
            float den = dn * cn + 1e-8f;
            float ang = 1.0f - fabsf(num / den);
            float ssum = dy + nrmv + ang;
            xb[(lane + 1) * 64 + 0] = dy + ssum;
            xb[(lane + 1) * 64 + 1] = nrmv + ssum;
            xb[(lane + 1) * 64 + 2] = ang + ssum;
        }
        __syncwarp();

        ull r[9];
        {
            ull b2 = *(const ull*)(bia + 2 * lane);
            ull acc[9];
#pragma unroll
            for (int t = 0; t < 9; t++) acc[t] = b2;
#pragma unroll
            for (int c = 0; c < 3; c++) {
                float xv[9];                    // padded rows 1..9
#pragma unroll
                for (int j = 0; j < 9; j++) xv[j] = xb[(j + 1) * 64 + c];
#pragma unroll
                for (int k = 0; k < 3; k++) {
                    ull wk = *(const ull*)(w0a + (k * 3 + c) * 64 + 2 * lane);
#pragma unroll
                    for (int t = 0; t < 9; t++) {
                        int row = t + k;
                        if (row >= 1 && row <= 9)
                            acc[t] = fma2(dup2(xv[row - 1]), wk, acc[t]);
                    }
                }
            }
#pragma unroll
            for (int t = 0; t < 9; t++) {
                float lo, hi; upk(acc[t], lo, hi);
                r[t] = pk(fmaxf(lo, 0.f), fmaxf(hi, 0.f));
            }
        }
        conv_residual(r, W,         bia + 64,  xb, lane);
        conv_residual(r, W + 12288, bia + 128, xb, lane);

        __syncwarp();
#pragma unroll
        for (int t = 0; t < 9; t++) *(ull*)(xb + (t + 1) * 64 + 2 * lane) = r[t];
        __syncwarp();

        float* og = out + (size_t)g * 1152;
        ull am[9];
#pragma unroll
        for (int t = 0; t < 9; t++) am[t] = *(const ull*)(og + t * 128 + 2 * lane);
        mlp_pass(am, xb, mws, lane);

#pragma unroll
        for (int t = 0; t < 9; t++) {
            float lo, hi; upk(am[t], lo, hi);
            *(ull*)(og + t * 128 + 2 * lane) = pk(fmaxf(lo, 0.f), fmaxf(hi, 0.f));
        }
    }
}

extern "C" void kernel_launch(void* const* d_in, const int* in_sizes, int n_in,
                              void* d_out, int out_size)
{
    const float* pc    = (const float*)d_in[0];
    const float* feats = (const float*)d_in[1];
    // 2..13 = pos_* / rel_* (dead in the reference: pos_e/rel_e are discarded)
    const float* nw0 = (const float*)d_in[14];
    const float* nb0 = (const float*)d_in[15];
    const float* nw1 = (const float*)d_in[16];
    const float* nb1 = (const float*)d_in[17];
    const float* nw2 = (const float*)d_in[18];
    const float* nb2 = (const float*)d_in[19];
    const float* aw0 = (const float*)d_in[20];
    const float* ab0 = (const float*)d_in[21];
    const float* aw1 = (const float*)d_in[22];
    const float* ab1 = (const float*)d_in[23];
    const float* aw2 = (const float*)d_in[24];
    const float* ab2 = (const float*)d_in[25];
    const float* mw  = (const float*)d_in[26];
    const float* mb  = (const float*)d_in[27];

    const int ngroups = in_sizes[0] / 36;   // B*N groups of S=9 points x 4

    const int smem1 = (24576 + 192 + 192 + 64 + 4096 + 24 * 704) * 4;   // 184064
    const int smem2 = (24576 + 576 + 192 + 4096 + 24 * 704) * 4;        // 185344

    cudaFuncSetAttribute(locse_k1, cudaFuncAttributeMaxDynamicSharedMemorySize, smem1);
    cudaFuncSetAttribute(locse_k2, cudaFuncAttributeMaxDynamicSharedMemorySize, smem2);

    locse_k1<<<152, 768, smem1>>>(pc, feats, nw0, nb0, nw1, nb1, nw2, nb2,
                                  mw, mb, (float*)d_out, ngroups);
    locse_k2<<<152, 768, smem2>>>(pc, aw0, ab0, aw1, ab1, aw2, ab2,
                                  mw, (float*)d_out, ngroups);
}

// round 8
// speedup vs baseline: 1.6761x; 1.0004x over previous
#include <cuda_runtime.h>

// LocSE fused kernel, round 7: 768 threads (6 warps/SMSP) WITHOUT spills.
// Register diet vs R6: (a) r[] not held across the conv c-loop -- recomputed
// from xb (xb = r + s, s warp-uniform) after the loop; (b) zero-pad rows
// elided (9 activation loads, 25 FMA2 per c-iter instead of 11/27).
// Two-phase split (nrm+MLPhalf1 | ang+MLPhalf2) staging pre-relu via d_out.

typedef unsigned long long ull;

__device__ __forceinline__ ull pk(float lo, float hi) {
    ull r; asm("mov.b64 %0, {%1, %2};" : "=l"(r) : "f"(lo), "f"(hi)); return r;
}
__device__ __forceinline__ void upk(ull v, float& lo, float& hi) {
    asm("mov.b64 {%0, %1}, %2;" : "=f"(lo), "=f"(hi) : "l"(v));
}
__device__ __forceinline__ ull fma2(ull a, ull b, ull c) {
#if __CUDA_ARCH__ >= 1000
    ull d; asm("fma.rn.f32x2 %0, %1, %2, %3;" : "=l"(d) : "l"(a), "l"(b), "l"(c));
    return d;
#else
    float ax, ay, bx, by, cx, cy;
    upk(a, ax, ay); upk(b, bx, by); upk(c, cx, cy);
    return pk(fmaf(ax, bx, cx), fmaf(ay, by, cy));
#endif
}
__device__ __forceinline__ ull dup2(float v) { return pk(v, v); }

// One residual conv layer: r = r + relu(conv1d(r + sum_c(r), W) + b)
// On entry r[] holds this lane's 2 channels for 9 rows; on exit updated.
// xb: per-warp smem buffer, 11 rows x 64 ch (rows 0 and 10 permanent zero,
// never read here thanks to pad elision; kept for layer-0 compatibility).
__device__ __forceinline__ void conv_residual(ull r[9],
                                              const float* __restrict__ Wl,
                                              const float* __restrict__ bvec,
                                              float* __restrict__ xb, int lane)
{
    float s[9];
#pragma unroll
    for (int t = 0; t < 9; t++) { float lo, hi; upk(r[t], lo, hi); s[t] = lo + hi; }
#pragma unroll
    for (int off = 16; off >= 1; off >>= 1) {
#pragma unroll
        for (int t = 0; t < 9; t++) s[t] += __shfl_xor_sync(0xffffffffu, s[t], off);
    }
    __syncwarp();
#pragma unroll
    for (int t = 0; t < 9; t++) {
        float lo, hi; upk(r[t], lo, hi);
        *(ull*)(xb + (t + 1) * 64 + 2 * lane) = pk(lo + s[t], hi + s[t]);
    }
    __syncwarp();
    // r[] is dead from here until the tail -> ptxas can reuse its registers.

    ull acc[9];
    {
        ull b2 = *(const ull*)(bvec + 2 * lane);
#pragma unroll
        for (int t = 0; t < 9; t++) acc[t] = b2;
    }

#pragma unroll 2
    for (int c = 0; c < 64; c++) {
        ull xd[9];                               // padded rows 1..9 only
#pragma unroll
        for (int j = 0; j < 9; j++) xd[j] = dup2(xb[(j + 1) * 64 + c]);
#pragma unroll
        for (int k = 0; k < 3; k++) {
            ull wk = *(const ull*)(Wl + (k * 64 + c) * 64 + 2 * lane);
#pragma unroll
            for (int t = 0; t < 9; t++) {
                int row = t + k;                 // padded row index
                if (row >= 1 && row <= 9)        // compile-time pad elision
                    acc[t] = fma2(xd[row - 1], wk, acc[t]);
            }
        }
    }

    // tail: recover r = xb - s, add relu(acc)
#pragma unroll
    for (int t = 0; t < 9; t++) {
        ull xv = *(const ull*)(xb + (t + 1) * 64 + 2 * lane);
        float xlo, xhi; upk(xv, xlo, xhi);
        float alo, ahi; upk(acc[t], alo, ahi);
        r[t] = pk(xlo - s[t] + fmaxf(alo, 0.f),
                  xhi - s[t] + fmaxf(ahi, 0.f));
    }
}

// am += xb(rows 1..9 x 64) @ mws(64x64), weights in smem
__device__ __forceinline__ void mlp_pass(ull am[9], const float* __restrict__ xb,
                                         const float* __restrict__ mws, int lane)
{
#pragma unroll 4
    for (int c = 0; c < 64; c++) {
        ull w = *(const ull*)(mws + c * 64 + 2 * lane);
        ull xd[9];
#pragma unroll
        for (int t = 0; t < 9; t++) xd[t] = dup2(xb[(t + 1) * 64 + c]);
#pragma unroll
        for (int t = 0; t < 9; t++) am[t] = fma2(xd[t], w, am[t]);
    }
}

// ---------------------------------------------------------------------------
// Kernel 1: nrm tower + MLP half 1 -> out ch[0..63] (pre-relu) + feats copy
// ---------------------------------------------------------------------------
__global__ void __launch_bounds__(768, 1)
locse_k1(const float* __restrict__ pc, const float* __restrict__ feats,
         const float* __restrict__ nw0, const float* __restrict__ nb0,
         const float* __restrict__ nw1, const float* __restrict__ nb1,
         const float* __restrict__ nw2, const float* __restrict__ nb2,
         const float* __restrict__ mw, const float* __restrict__ mb,
         float* __restrict__ out, int ngroups)
{
    extern __shared__ float sm[];
    float* W   = sm;            // 2 * 12288 : [nrm_w1, nrm_w2]
    float* w0n = W + 24576;     // 192
    float* bia = w0n + 192;     // 192 : [nb0 nb1 nb2]
    float* mbs = bia + 192;     // 64
    float* mws = mbs + 64;      // 4096 : mlp_w rows 0..63
    float* xba = mws + 4096;    // 24 warps * 704 (11 rows x 64 ch)

    const int tid = threadIdx.x;
    for (int i = tid; i < 12288; i += 768) {
        W[i]         = nw1[i];
        W[12288 + i] = nw2[i];
    }
    for (int i = tid; i < 4096; i += 768) mws[i] = mw[i];
    if (tid < 192) w0n[tid] = nw0[tid];
    if (tid < 64) {
        bia[tid]       = nb0[tid];
        bia[64 + tid]  = nb1[tid];
        bia[128 + tid] = nb2[tid];
        mbs[tid]       = mb[tid];
    }
    const int warp = tid >> 5, lane = tid & 31;
    float* xb = xba + warp * 704;
    for (int i = lane; i < 64; i += 32) { xb[i] = 0.f; xb[640 + i] = 0.f; }
    __syncthreads();

    const int stride = gridDim.x * 24;
    for (int g = blockIdx.x * 24 + warp; g < ngroups; g += stride) {
        __syncwarp();
        if (lane < 9) {
            const float4 p  = *(const float4*)(pc + (size_t)g * 36 + lane * 4);
            const float4 cc = *(const float4*)(pc + (size_t)g * 36);
            float dx = cc.x - p.x;
            xb[(lane + 1) * 64] = 2.0f * dx;   // x + sum_c(x) with cin=1 -> 2x
        }
        __syncwarp();

        ull r[9];
        {
            ull b2 = *(const ull*)(bia + 2 * lane);
            ull acc[9];
#pragma unroll
            for (int t = 0; t < 9; t++) acc[t] = b2;
            float xv[9];                        // padded rows 1..9
#pragma unroll
            for (int j = 0; j < 9; j++) xv[j] = xb[(j + 1) * 64];
#pragma unroll
            for (int k = 0; k < 3; k++) {
                ull wk = *(const ull*)(w0n + k * 64 + 2 * lane);
#pragma unroll
                for (int t = 0; t < 9; t++) {
                    int row = t + k;
                    if (row >= 1 && row <= 9)
                        acc[t] = fma2(dup2(xv[row - 1]), wk, acc[t]);
                }
            }
#pragma unroll
            for (int t = 0; t < 9; t++) {
                float lo, hi; upk(acc[t], lo, hi);
                r[t] = pk(fmaxf(lo, 0.f), fmaxf(hi, 0.f));
            }
        }
        conv_residual(r, W,         bia + 64,  xb, lane);
        conv_residual(r, W + 12288, bia + 128, xb, lane);

        __syncwarp();
#pragma unroll
        for (int t = 0; t < 9; t++) *(ull*)(xb + (t + 1) * 64 + 2 * lane) = r[t];
        __syncwarp();

        ull am[9];
        {
            ull b2 = *(const ull*)(mbs + 2 * lane);
#pragma unroll
            for (int t = 0; t < 9; t++) am[t] = b2;
        }
        mlp_pass(am, xb, mws, lane);

        // stage pre-relu partial into out ch[0..63]; feats into ch[64..127]
        float* og = out + (size_t)g * 1152;
#pragma unroll
        for (int t = 0; t < 9; t++) *(ull*)(og + t * 128 + 2 * lane) = am[t];

        const float4* f4 = (const float4*)(feats + (size_t)g * 576);
        float4* o4 = (float4*)og;
        for (int i = lane; i < 144; i += 32) {
            int row = i >> 4, col = i & 15;
            o4[row * 32 + 16 + col] = f4[i];
        }
    }
}

// ---------------------------------------------------------------------------
// Kernel 2: ang tower + MLP half 2; out ch[0..63] += , then relu
// ---------------------------------------------------------------------------
__global__ void __launch_bounds__(768, 1)
locse_k2(const float* __restrict__ pc,
         const float* __restrict__ aw0, const float* __restrict__ ab0,
         const float* __restrict__ aw1, const float* __restrict__ ab1,
         const float* __restrict__ aw2, const float* __restrict__ ab2,
         const float* __restrict__ mw,
         float* __restrict__ out, int ngroups)
{
    extern __shared__ float sm[];
    float* W   = sm;            // 2 * 12288 : [ang_w1, ang_w2]
    float* w0a = W + 24576;     // 576
    float* bia = w0a + 576;     // 192 : [ab0 ab1 ab2]
    float* mws = bia + 192;     // 4096 : mlp_w rows 64..127
    float* xba = mws + 4096;    // 24 warps * 704

    const int tid = threadIdx.x;
    for (int i = tid; i < 12288; i += 768) {
        W[i]         = aw1[i];
        W[12288 + i] = aw2[i];
    }
    for (int i = tid; i < 4096; i += 768) mws[i] = mw[4096 + i];
    if (tid < 576) w0a[tid] = aw0[tid];
    if (tid < 64) {
        bia[tid]       = ab0[tid];
        bia[64 + tid]  = ab1[tid];
        bia[128 + tid] = ab2[tid];
    }
    const int warp = tid >> 5, lane = tid & 31;
    float* xb = xba + warp * 704;
    for (int i = lane; i < 64; i += 32) { xb[i] = 0.f; xb[640 + i] = 0.f; }
    __syncthreads();

    const int stride = gridDim.x * 24;
    for (int g = blockIdx.x * 24 + warp; g < ngroups; g += stride) {
        __syncwarp();
        if (lane < 9) {
            const float4 p  = *(const float4*)(pc + (size_t)g * 36 + lane * 4);
            const float4 cc = *(const float4*)(pc + (size_t)g * 36);
            float dx = cc.x - p.x, dy = cc.y - p.y;
            float s1 = p.x * p.x + p.y * p.y;
            float nrmv = (s1 > 0.f) ? sqrtf(s1) : 0.f;
            float s2 = dx * dx + dy * dy;
            float dn = (s2 > 0.f) ? sqrtf(s2) : 0.f;
            float s3 = cc.x * cc.x + cc.y * cc.y + cc.z * cc.z + cc.w * cc.w;
            float cn = (s3 > 0.f) ? sqrtf(s3) : 0.f;
            float num = dx * cc.z + dy * cc.w;
            float den = dn * cn + 1e-8f;
            float ang = 1.0f - fabsf(num / den);
            float ssum = dy + nrmv + ang;
            xb[(lane + 1) * 64 + 0] = dy + ssum;
            xb[(lane + 1) * 64 + 1] = nrmv + ssum;
            xb[(lane + 1) * 64 + 2] = ang + ssum;
        }
        __syncwarp();

        ull r[9];
        {
            ull b2 = *(const ull*)(bia + 2 * lane);
            ull acc[9];
#pragma unroll
            for (int t = 0; t < 9; t++) acc[t] = b2;
#pragma unroll
            for (int c = 0; c < 3; c++) {
                float xv[9];                    // padded rows 1..9
#pragma unroll
                for (int j = 0; j < 9; j++) xv[j] = xb[(j + 1) * 64 + c];
#pragma unroll
                for (int k = 0; k < 3; k++) {
                    ull wk = *(const ull*)(w0a + (k * 3 + c) * 64 + 2 * lane);
#pragma unroll
                    for (int t = 0; t < 9; t++) {
                        int row = t + k;
                        if (row >= 1 && row <= 9)
                            acc[t] = fma2(dup2(xv[row - 1]), wk, acc[t]);
                    }
                }
            }
#pragma unroll
            for (int t = 0; t < 9; t++) {
                float lo, hi; upk(acc[t], lo, hi);
                r[t] = pk(fmaxf(lo, 0.f), fmaxf(hi, 0.f));
            }
        }
        conv_residual(r, W,         bia + 64,  xb, lane);
        conv_residual(r, W + 12288, bia + 128, xb, lane);

        __syncwarp();
#pragma unroll
        for (int t = 0; t < 9; t++) *(ull*)(xb + (t + 1) * 64 + 2 * lane) = r[t];
        __syncwarp();

        float* og = out + (size_t)g * 1152;
        ull am[9];
#pragma unroll
        for (int t = 0; t < 9; t++) am[t] = *(const ull*)(og + t * 128 + 2 * lane);
        mlp_pass(am, xb, mws, lane);

#pragma unroll
        for (int t = 0; t < 9; t++) {
            float lo, hi; upk(am[t], lo, hi);
            *(ull*)(og + t * 128 + 2 * lane) = pk(fmaxf(lo, 0.f), fmaxf(hi, 0.f));
        }
    }
}

extern "C" void kernel_launch(void* const* d_in, const int* in_sizes, int n_in,
                              void* d_out, int out_size)
{
    const float* pc    = (const float*)d_in[0];
    const float* feats = (const float*)d_in[1];
    // 2..13 = pos_* / rel_* (dead in the reference: pos_e/rel_e are discarded)
    const float* nw0 = (const float*)d_in[14];
    const float* nb0 = (const float*)d_in[15];
    const float* nw1 = (const float*)d_in[16];
    const float* nb1 = (const float*)d_in[17];
    const float* nw2 = (const float*)d_in[18];
    const float* nb2 = (const float*)d_in[19];
    const float* aw0 = (const float*)d_in[20];
    const float* ab0 = (const float*)d_in[21];
    const float* aw1 = (const float*)d_in[22];
    const float* ab1 = (const float*)d_in[23];
    const float* aw2 = (const float*)d_in[24];
    const float* ab2 = (const float*)d_in[25];
    const float* mw  = (const float*)d_in[26];
    const float* mb  = (const float*)d_in[27];

    const int ngroups = in_sizes[0] / 36;   // B*N groups of S=9 points x 4

    const int smem1 = (24576 + 192 + 192 + 64 + 4096 + 24 * 704) * 4;   // 184064
    const int smem2 = (24576 + 576 + 192 + 4096 + 24 * 704) * 4;        // 185344

    cudaFuncSetAttribute(locse_k1, cudaFuncAttributeMaxDynamicSharedMemorySize, smem1);
    cudaFuncSetAttribute(locse_k2, cudaFuncAttributeMaxDynamicSharedMemorySize, smem2);

    locse_k1<<<152, 768, smem1>>>(pc, feats, nw0, nb0, nw1, nb1, nw2, nb2,
                                  mw, mb, (float*)d_out, ngroups);
    locse_k2<<<152, 768, smem2>>>(pc, aw0, ab0, aw1, ab1, aw2, ab2,
                                  mw, (float*)d_out, ngroups);
}